// round 9
// baseline (speedup 1.0000x reference)
#include <cuda_runtime.h>
#include <math.h>
#include <stdint.h>

#define NN 50000
#define EE 800000
#define GG 256
#define DD 128
#define FF 1792   // 14*128
#define BN_EPS 1e-5f
#define NB_SCAN 196  // ceil(NN/256)

typedef unsigned long long ull;

// ---------------- scratch (device globals) ----------------
__device__ float g_t1[(size_t)NN * DD];
__device__ float g_h[(size_t)NN * DD];
__device__ float g_feat[(size_t)GG * FF];
__device__ float g_feat2[(size_t)GG * FF];
__device__ float g_sum[DD];
__device__ float g_sqsum[DD];
__device__ float g_scale[DD];
__device__ float g_shift[DD];
// CSR scratch
__device__ int g_deg[NN];
__device__ int g_cursor[NN];
__device__ int g_rowptr[NN + 1];
__device__ int g_esrc[EE];
__device__ int g_bsum[256];

// ---------------- f32x2 helpers ----------------
__device__ __forceinline__ ull pk2(float x) {
    ull r;
    asm("mov.b64 %0, {%1,%2};" : "=l"(r) : "f"(x), "f"(x));
    return r;
}
__device__ __forceinline__ void fma2(ull& d, ull a, ull b) {
    asm("fma.rn.f32x2 %0, %1, %2, %0;" : "+l"(d) : "l"(a), "l"(b));
}
__device__ __forceinline__ void unpk(ull v, float& lo, float& hi) {
    asm("mov.b64 {%0,%1}, %2;" : "=f"(lo), "=f"(hi) : "l"(v));
}

// ---------------- zero g_feat ----------------
__global__ void k_zero_feat() {
    int i = blockIdx.x * blockDim.x + threadIdx.x;
    if (i < GG * FF) g_feat[i] = 0.f;
}

// ---------------- CSR build ----------------
__global__ void k_zero_csr() {
    int i = blockIdx.x * blockDim.x + threadIdx.x;
    if (i < NN) { g_deg[i] = 0; g_cursor[i] = 0; }
}
__global__ void k_hist(const int* __restrict__ dst) {
    int e = blockIdx.x * blockDim.x + threadIdx.x;
    if (e < EE) atomicAdd(&g_deg[dst[e]], 1);
}
__global__ void k_scan1() {
    __shared__ int sh[256];
    int t = threadIdx.x;
    int i = blockIdx.x * 256 + t;
    int v = (i < NN) ? g_deg[i] : 0;
    sh[t] = v;
    __syncthreads();
#pragma unroll
    for (int off = 1; off < 256; off <<= 1) {
        int a = (t >= off) ? sh[t - off] : 0;
        __syncthreads();
        sh[t] += a;
        __syncthreads();
    }
    if (i < NN) g_rowptr[i] = sh[t] - v;
    if (t == 255) g_bsum[blockIdx.x] = sh[255];
}
__global__ void k_scan2() {
    __shared__ int sh[256];
    int t = threadIdx.x;
    int v = (t < NB_SCAN) ? g_bsum[t] : 0;
    sh[t] = v;
    __syncthreads();
#pragma unroll
    for (int off = 1; off < 256; off <<= 1) {
        int a = (t >= off) ? sh[t - off] : 0;
        __syncthreads();
        sh[t] += a;
        __syncthreads();
    }
    if (t < NB_SCAN) g_bsum[t] = sh[t] - v;
}
__global__ void k_scan3() {
    int i = blockIdx.x * blockDim.x + threadIdx.x;
    if (i < NN) g_rowptr[i] += g_bsum[i >> 8];
    if (i == 0) g_rowptr[NN] = EE;
}
__global__ void k_fill(const int* __restrict__ src, const int* __restrict__ dst) {
    int e = blockIdx.x * blockDim.x + threadIdx.x;
    if (e >= EE) return;
    int d = dst[e];
    int pos = atomicAdd(&g_cursor[d], 1);
    g_esrc[g_rowptr[d] + pos] = src[e];
}

// =====================================================================
// FUSED agg+GEMM1: C[128tile,128] = (h + sum_in h) @ W + bias
// A gathered directly into row-major smem As[128][132]; B double-buffered
// k-major. Mainloop: A via warp-broadcast LDS.64 (2 k-steps), B via c0/c1
// conflict-free LDS.128. Epilogue: fused BN column stats.
// =====================================================================
#define AGG_SMEM ((128 * 132 + 2 * 16 * 128) * 4)   // 83968 B

__global__ void __launch_bounds__(256, 2)
k_gemmAgg(const float* __restrict__ h, const float* __restrict__ W,
          const float* __restrict__ bias, float* __restrict__ C) {
    extern __shared__ float sm[];
    float* As = sm;                                   // [128][132] row-major
    float (*Bs)[16][128] = reinterpret_cast<float (*)[16][128]>(sm + 128 * 132);

    const int tid = threadIdx.x;
    const int tx = tid & 15, ty = tid >> 4;
    const int wid = tid >> 5, lane = tid & 31;
    const int row0 = blockIdx.x * 128;
    const int c0 = tx * 4, c1 = 64 + tx * 4;

    float4 rb[2];
    auto ldgB = [&](int k0) {
#pragma unroll
        for (int i = 0; i < 2; i++) {
            int v = tid + 256 * i;
            int kr = v >> 5, c4 = (v & 31) * 4;
            rb[i] = *reinterpret_cast<const float4*>(W + (size_t)(k0 + kr) * DD + c4);
        }
    };
    auto stsB = [&](int s) {
#pragma unroll
        for (int i = 0; i < 2; i++) {
            int v = tid + 256 * i;
            int kr = v >> 5, c4 = (v & 31) * 4;
            *reinterpret_cast<float4*>(&Bs[s][kr][c4]) = rb[i];
        }
    };

    ldgB(0);  // prefetch B chunk 0 while gathering A

    // ---- gather phase: warp w handles rows w*16..w*16+15 ----
    const float4* __restrict__ h4 = reinterpret_cast<const float4*>(h);
    for (int i = 0; i < 16; i++) {
        int row = wid * 16 + i;
        int gr = row0 + row;
        float4 acc = make_float4(0.f, 0.f, 0.f, 0.f);
        if (gr < NN) {
            acc = h4[(size_t)gr * 32 + lane];
            int s = g_rowptr[gr], e = g_rowptr[gr + 1];
            int j = s;
            for (; j + 4 <= e; j += 4) {
                int i0 = g_esrc[j], i1 = g_esrc[j + 1], i2 = g_esrc[j + 2], i3 = g_esrc[j + 3];
                float4 v0 = h4[(size_t)i0 * 32 + lane];
                float4 v1 = h4[(size_t)i1 * 32 + lane];
                float4 v2 = h4[(size_t)i2 * 32 + lane];
                float4 v3 = h4[(size_t)i3 * 32 + lane];
                acc.x += v0.x + v1.x + v2.x + v3.x;
                acc.y += v0.y + v1.y + v2.y + v3.y;
                acc.z += v0.z + v1.z + v2.z + v3.z;
                acc.w += v0.w + v1.w + v2.w + v3.w;
            }
            for (; j < e; j++) {
                int i0 = g_esrc[j];
                float4 v0 = h4[(size_t)i0 * 32 + lane];
                acc.x += v0.x; acc.y += v0.y; acc.z += v0.z; acc.w += v0.w;
            }
        }
        *reinterpret_cast<float4*>(&As[row * 132 + lane * 4]) = acc;  // STS.128, conflict-free
    }
    stsB(0);
    __syncthreads();

    // ---- mainloop: 8 chunks of BK=16; A row-major broadcast, B pipelined ----
    ull acc[8][4];
#pragma unroll
    for (int i = 0; i < 8; i++)
#pragma unroll
        for (int j = 0; j < 4; j++) acc[i][j] = 0ull;

    int s = 0;
#pragma unroll
    for (int t = 0; t < 8; t++) {
        if (t < 7) ldgB((t + 1) * 16);
#pragma unroll
        for (int kk = 0; kk < 16; kk += 2) {
            int kg = t * 16 + kk;
            float2 av[8];
#pragma unroll
            for (int i = 0; i < 8; i++)
                av[i] = *reinterpret_cast<const float2*>(&As[(ty * 8 + i) * 132 + kg]);
            // k-step kk
            {
                ulonglong2 bv0 = *reinterpret_cast<const ulonglong2*>(&Bs[s][kk][c0]);
                ulonglong2 bv1 = *reinterpret_cast<const ulonglong2*>(&Bs[s][kk][c1]);
                ull bu[4] = {bv0.x, bv0.y, bv1.x, bv1.y};
#pragma unroll
                for (int i = 0; i < 8; i++) {
                    ull au = pk2(av[i].x);
                    fma2(acc[i][0], au, bu[0]);
                    fma2(acc[i][1], au, bu[1]);
                    fma2(acc[i][2], au, bu[2]);
                    fma2(acc[i][3], au, bu[3]);
                }
            }
            // k-step kk+1
            {
                ulonglong2 bv0 = *reinterpret_cast<const ulonglong2*>(&Bs[s][kk + 1][c0]);
                ulonglong2 bv1 = *reinterpret_cast<const ulonglong2*>(&Bs[s][kk + 1][c1]);
                ull bu[4] = {bv0.x, bv0.y, bv1.x, bv1.y};
#pragma unroll
                for (int i = 0; i < 8; i++) {
                    ull au = pk2(av[i].y);
                    fma2(acc[i][0], au, bu[0]);
                    fma2(acc[i][1], au, bu[1]);
                    fma2(acc[i][2], au, bu[2]);
                    fma2(acc[i][3], au, bu[3]);
                }
            }
        }
        if (t < 7) stsB(s ^ 1);
        __syncthreads();
        s ^= 1;
    }

    // ---- epilogue: bias, store C, fused BN column stats ----
    float bb[8];
#pragma unroll
    for (int j = 0; j < 4; j++) { bb[j] = bias[c0 + j]; bb[4 + j] = bias[c1 + j]; }

    float cs[8], cq[8];
#pragma unroll
    for (int j = 0; j < 8; j++) { cs[j] = 0.f; cq[j] = 0.f; }
#pragma unroll
    for (int i = 0; i < 8; i++) {
        float o[8];
#pragma unroll
        for (int j = 0; j < 4; j++) unpk(acc[i][j], o[2 * j], o[2 * j + 1]);
        int gr = row0 + ty * 8 + i;
        if (gr < NN) {
#pragma unroll
            for (int j = 0; j < 8; j++) {
                o[j] += bb[j];
                cs[j] += o[j];
                cq[j] = fmaf(o[j], o[j], cq[j]);
            }
            float* cp = C + (size_t)gr * DD;
            *reinterpret_cast<float4*>(cp + c0) = *reinterpret_cast<const float4*>(&o[0]);
            *reinterpret_cast<float4*>(cp + c1) = *reinterpret_cast<const float4*>(&o[4]);
        }
    }

    __syncthreads();
    float* reds = sm;            // [16][128]
    float* redq = sm + 2048;
#pragma unroll
    for (int j = 0; j < 4; j++) {
        reds[ty * 128 + c0 + j] = cs[j];
        reds[ty * 128 + c1 + j] = cs[4 + j];
        redq[ty * 128 + c0 + j] = cq[j];
        redq[ty * 128 + c1 + j] = cq[4 + j];
    }
    __syncthreads();
    if (tid < 128) {
        float ssum = 0.f, sq = 0.f;
#pragma unroll
        for (int r = 0; r < 16; r++) {
            ssum += reds[r * 128 + tid];
            sq += redq[r * 128 + tid];
        }
        atomicAdd(&g_sum[tid], ssum);
        atomicAdd(&g_sqsum[tid], sq);
    }
}

// =====================================================================
// GEMM2 (unchanged R7): BN+relu prologue, relu out, fused readout
// =====================================================================
#define GEMM_SMEM (128 * 136 * 4)   // 69632 B

__global__ void __launch_bounds__(256, 2)
k_gemm2(const float* __restrict__ A, const float* __restrict__ W,
        const float* __restrict__ bias, float* __restrict__ C,
        const int* __restrict__ batch, int layer) {
    extern __shared__ float sm[];
    float (*As)[16][128] = reinterpret_cast<float (*)[16][128]>(sm);
    float (*Bs)[16][128] = reinterpret_cast<float (*)[16][128]>(sm + 4096);
    __shared__ int bt[128];

    const int tid = threadIdx.x;
    const int tx = tid & 15, ty = tid >> 4;
    const int row0 = blockIdx.x * 128;
    const int c0 = tx * 4, c1 = 64 + tx * 4;

    if (tid < 128) {
        int gr = row0 + tid;
        bt[tid] = (gr < NN) ? batch[gr] : -1;
    }

    ull acc[8][4];
#pragma unroll
    for (int i = 0; i < 8; i++)
#pragma unroll
        for (int j = 0; j < 4; j++) acc[i][j] = 0ull;

    float4 ra[2], rb[2];

    auto ldg = [&](int k0) {
#pragma unroll
        for (int i = 0; i < 2; i++) {
            int v = tid + 256 * i;
            int r = v >> 2, kq = (v & 3) * 4;
            int gr = row0 + r;
            float4 val = make_float4(0.f, 0.f, 0.f, 0.f);
            if (gr < NN) val = *reinterpret_cast<const float4*>(A + (size_t)gr * DD + k0 + kq);
            float4 sc = *reinterpret_cast<const float4*>(g_scale + k0 + kq);
            float4 sh = *reinterpret_cast<const float4*>(g_shift + k0 + kq);
            val.x = fmaxf(fmaf(val.x, sc.x, sh.x), 0.f);
            val.y = fmaxf(fmaf(val.y, sc.y, sh.y), 0.f);
            val.z = fmaxf(fmaf(val.z, sc.z, sh.z), 0.f);
            val.w = fmaxf(fmaf(val.w, sc.w, sh.w), 0.f);
            ra[i] = val;
            int kr = v >> 5, c4 = (v & 31) * 4;
            rb[i] = *reinterpret_cast<const float4*>(W + (size_t)(k0 + kr) * DD + c4);
        }
    };
    auto sts = [&](int s) {
#pragma unroll
        for (int i = 0; i < 2; i++) {
            int v = tid + 256 * i;
            int r = v >> 2, kq = (v & 3) * 4;
            As[s][kq + 0][r] = ra[i].x;
            As[s][kq + 1][r] = ra[i].y;
            As[s][kq + 2][r] = ra[i].z;
            As[s][kq + 3][r] = ra[i].w;
            int kr = v >> 5, c4 = (v & 31) * 4;
            *reinterpret_cast<float4*>(&Bs[s][kr][c4]) = rb[i];
        }
    };

    ldg(0);
    sts(0);
    __syncthreads();
    int s = 0;
#pragma unroll
    for (int t = 0; t < 8; t++) {
        if (t < 7) ldg((t + 1) * 16);
#pragma unroll
        for (int kk = 0; kk < 16; kk++) {
            float4 a0 = *reinterpret_cast<const float4*>(&As[s][kk][ty * 8]);
            float4 a1 = *reinterpret_cast<const float4*>(&As[s][kk][ty * 8 + 4]);
            ulonglong2 bv0 = *reinterpret_cast<const ulonglong2*>(&Bs[s][kk][c0]);
            ulonglong2 bv1 = *reinterpret_cast<const ulonglong2*>(&Bs[s][kk][c1]);
            ull bu[4] = {bv0.x, bv0.y, bv1.x, bv1.y};
            ull au[8];
            au[0] = pk2(a0.x); au[1] = pk2(a0.y); au[2] = pk2(a0.z); au[3] = pk2(a0.w);
            au[4] = pk2(a1.x); au[5] = pk2(a1.y); au[6] = pk2(a1.z); au[7] = pk2(a1.w);
#pragma unroll
            for (int i = 0; i < 8; i++) {
                fma2(acc[i][0], au[i], bu[0]);
                fma2(acc[i][1], au[i], bu[1]);
                fma2(acc[i][2], au[i], bu[2]);
                fma2(acc[i][3], au[i], bu[3]);
            }
        }
        if (t < 7) sts(s ^ 1);
        __syncthreads();
        s ^= 1;
    }

    float bb[8];
#pragma unroll
    for (int j = 0; j < 4; j++) { bb[j] = bias[c0 + j]; bb[4 + j] = bias[c1 + j]; }

    float o[8][8];
#pragma unroll
    for (int i = 0; i < 8; i++) {
#pragma unroll
        for (int j = 0; j < 4; j++) unpk(acc[i][j], o[i][2 * j], o[i][2 * j + 1]);
        int gr = row0 + ty * 8 + i;
        bool ok = (gr < NN);
#pragma unroll
        for (int j = 0; j < 8; j++) {
            float v = fmaxf(o[i][j] + bb[j], 0.f);
            if (!ok) v = 0.f;
            o[i][j] = v;
        }
        if (ok) {
            float* cp = C + (size_t)gr * DD;
            *reinterpret_cast<float4*>(cp + c0) = *reinterpret_cast<const float4*>(&o[i][0]);
            *reinterpret_cast<float4*>(cp + c1) = *reinterpret_cast<const float4*>(&o[i][4]);
        }
    }

    __syncthreads();
    float* st = sm;   // [128][136]
#pragma unroll
    for (int i = 0; i < 8; i++) {
        int row = ty * 8 + i;
        *reinterpret_cast<float4*>(&st[row * 136 + c0]) = *reinterpret_cast<const float4*>(&o[i][0]);
        *reinterpret_cast<float4*>(&st[row * 136 + c1]) = *reinterpret_cast<const float4*>(&o[i][4]);
    }
    __syncthreads();
    int col = tid & 127;
    int half = tid >> 7;
    int rs = half * 64, re = rs + 64;
    float* fsum = g_feat + (size_t)layer * DD + col;
    float* fmax = g_feat + (size_t)(7 * DD + layer * DD) + col;
    int cur = -1;
    float ssum = 0.f, mx = 0.f;
    for (int r = rs; r < re; r++) {
        int g = bt[r];
        if (g != cur) {
            if (cur >= 0) {
                atomicAdd(fsum + (size_t)cur * FF, ssum);
                atomicMax((int*)(fmax + (size_t)cur * FF), __float_as_int(mx));
            }
            cur = g; ssum = 0.f; mx = 0.f;
        }
        if (g >= 0) {
            float v = st[r * 136 + col];
            ssum += v;
            mx = fmaxf(mx, v);
        }
    }
    if (cur >= 0) {
        atomicAdd(fsum + (size_t)cur * FF, ssum);
        atomicMax((int*)(fmax + (size_t)cur * FF), __float_as_int(mx));
    }
}

// ---------------- BN finalize ----------------
__global__ void k_bnfin(const float* __restrict__ gamma, const float* __restrict__ beta) {
    int c = threadIdx.x;
    float m = g_sum[c] * (1.f / NN);
    float var = g_sqsum[c] * (1.f / NN) - m * m;
    float sc = gamma[c] * rsqrtf(var + BN_EPS);
    g_scale[c] = sc;
    g_shift[c] = beta[c] - m * sc;
    g_sum[c] = 0.f;
    g_sqsum[c] = 0.f;
}

// ---------------- MLP layer 1 (R7) ----------------
__global__ void __launch_bounds__(256, 4)
k_gemm_mlp(const float* __restrict__ Afeat, const float* __restrict__ W,
           const float* __restrict__ bias, float* __restrict__ C) {
    __shared__ float As[2][16][32];
    __shared__ float Bs[2][16][128];
    const int tid = threadIdx.x;
    const int tx = tid & 15, ty = tid >> 4;
    const int row0 = blockIdx.y * 32;
    const int col0 = blockIdx.x * 128;
    const int c0 = tx * 4, c1 = 64 + tx * 4;

    ull acc[2][4];
#pragma unroll
    for (int i = 0; i < 2; i++)
#pragma unroll
        for (int j = 0; j < 4; j++) acc[i][j] = 0ull;

    float4 ra;
    float4 rb[2];

    auto ldg = [&](int k0) {
        if (tid < 128) {
            int r = tid >> 2, kq = (tid & 3) * 4;
            ra = *reinterpret_cast<const float4*>(Afeat + (size_t)(row0 + r) * FF + k0 + kq);
        }
#pragma unroll
        for (int i = 0; i < 2; i++) {
            int v = tid + 256 * i;
            int kr = v >> 5, c4 = (v & 31) * 4;
            rb[i] = *reinterpret_cast<const float4*>(W + (size_t)(k0 + kr) * FF + col0 + c4);
        }
    };
    auto sts = [&](int s) {
        if (tid < 128) {
            int r = tid >> 2, kq = (tid & 3) * 4;
            As[s][kq + 0][r] = ra.x;
            As[s][kq + 1][r] = ra.y;
            As[s][kq + 2][r] = ra.z;
            As[s][kq + 3][r] = ra.w;
        }
#pragma unroll
        for (int i = 0; i < 2; i++) {
            int v = tid + 256 * i;
            int kr = v >> 5, c4 = (v & 31) * 4;
            *reinterpret_cast<float4*>(&Bs[s][kr][c4]) = rb[i];
        }
    };

    ldg(0);
    sts(0);
    __syncthreads();
    int s = 0;
    const int NT = FF / 16;  // 112
    for (int t = 0; t < NT; t++) {
        if (t < NT - 1) ldg((t + 1) * 16);
#pragma unroll
        for (int kk = 0; kk < 16; kk++) {
            ull a0 = pk2(As[s][kk][ty * 2]);
            ull a1 = pk2(As[s][kk][ty * 2 + 1]);
            ulonglong2 bv0 = *reinterpret_cast<const ulonglong2*>(&Bs[s][kk][c0]);
            ulonglong2 bv1 = *reinterpret_cast<const ulonglong2*>(&Bs[s][kk][c1]);
            ull bu[4] = {bv0.x, bv0.y, bv1.x, bv1.y};
#pragma unroll
            for (int j = 0; j < 4; j++) {
                fma2(acc[0][j], a0, bu[j]);
                fma2(acc[1][j], a1, bu[j]);
            }
        }
        if (t < NT - 1) sts(s ^ 1);
        __syncthreads();
        s ^= 1;
    }
#pragma unroll
    for (int i = 0; i < 2; i++) {
        int gr = row0 + ty * 2 + i;
        float* cp = C + (size_t)gr * FF + col0;
        float o[8];
#pragma unroll
        for (int j = 0; j < 4; j++) unpk(acc[i][j], o[2 * j], o[2 * j + 1]);
#pragma unroll
        for (int j = 0; j < 4; j++) {
            o[j]     = fmaxf(o[j] + bias[col0 + c0 + j], 0.f);
            o[4 + j] = fmaxf(o[4 + j] + bias[col0 + c1 + j], 0.f);
        }
        *reinterpret_cast<float4*>(cp + c0) = *reinterpret_cast<const float4*>(&o[0]);
        *reinterpret_cast<float4*>(cp + c1) = *reinterpret_cast<const float4*>(&o[4]);
    }
}

// ---------------- head ----------------
__global__ void k_head(const float* __restrict__ Wl2, const float* __restrict__ bl2,
                       float* __restrict__ out) {
    int g = blockIdx.x;
    float p = 0.f;
    for (int k = threadIdx.x; k < FF; k += 256)
        p += g_feat2[(size_t)g * FF + k] * Wl2[k];
    __shared__ float red[256];
    red[threadIdx.x] = p;
    __syncthreads();
    for (int off = 128; off > 0; off >>= 1) {
        if (threadIdx.x < off) red[threadIdx.x] += red[threadIdx.x + off];
        __syncthreads();
    }
    if (threadIdx.x == 0) {
        float l = red[0] + bl2[0];
        out[g] = 1.f / (1.f + expf(-l));
        out[GG + g] = l;
    }
}

// ---------------- launch ----------------
extern "C" void kernel_launch(void* const* d_in, const int* in_sizes, int n_in,
                              void* d_out, int out_size) {
    const float* x     = (const float*)d_in[0];
    const int*   ei    = (const int*)d_in[1];
    const int*   batch = (const int*)d_in[2];
    const float* W1    = (const float*)d_in[3];
    const float* b1    = (const float*)d_in[4];
    const float* gamma = (const float*)d_in[5];
    const float* beta  = (const float*)d_in[6];
    const float* W2    = (const float*)d_in[7];
    const float* b2    = (const float*)d_in[8];
    const float* Wl1   = (const float*)d_in[9];
    const float* bl1   = (const float*)d_in[10];
    const float* Wl2   = (const float*)d_in[11];
    const float* bl2   = (const float*)d_in[12];
    float* out = (float*)d_out;

    const int* src = ei;
    const int* dst = ei + EE;

    float *t1p, *hp, *featp, *feat2p;
    cudaGetSymbolAddress((void**)&t1p, g_t1);
    cudaGetSymbolAddress((void**)&hp, g_h);
    cudaGetSymbolAddress((void**)&featp, g_feat);
    cudaGetSymbolAddress((void**)&feat2p, g_feat2);

    cudaFuncSetAttribute(k_gemmAgg, cudaFuncAttributeMaxDynamicSharedMemorySize, AGG_SMEM);
    cudaFuncSetAttribute(k_gemm2, cudaFuncAttributeMaxDynamicSharedMemorySize, GEMM_SMEM);

    k_zero_feat<<<(GG * FF + 255) / 256, 256>>>();

    // CSR build
    k_zero_csr<<<(NN + 255) / 256, 256>>>();
    k_hist<<<(EE + 255) / 256, 256>>>(dst);
    k_scan1<<<NB_SCAN, 256>>>();
    k_scan2<<<1, 256>>>();
    k_scan3<<<(NN + 255) / 256, 256>>>();
    k_fill<<<(EE + 255) / 256, 256>>>(src, dst);

    const int NBLK = (NN + 127) / 128;  // 391
    const float* hin = x;
    for (int l = 0; l < 7; l++) {
        k_gemmAgg<<<NBLK, 256, AGG_SMEM>>>(hin, W1 + (size_t)l * DD * DD,
                                           b1 + l * DD, t1p);
        k_bnfin<<<1, 128>>>(gamma + l * DD, beta + l * DD);
        k_gemm2<<<NBLK, 256, GEMM_SMEM>>>(t1p, W2 + (size_t)l * DD * DD,
                                          b2 + l * DD, hp, batch, l);
        hin = hp;
    }
    k_gemm_mlp<<<dim3(FF / 128, GG / 32), 256>>>(featp, Wl1, bl1, feat2p);
    k_head<<<GG, 256>>>(Wl2, bl2, out);
}

// round 10
// speedup vs baseline: 1.2023x; 1.2023x over previous
#include <cuda_runtime.h>
#include <math.h>
#include <stdint.h>

#define NN 50000
#define EE 800000
#define GG 256
#define DD 128
#define FF 1792   // 14*128
#define BN_EPS 1e-5f
#define NB_SCAN 196  // ceil(NN/256)

typedef unsigned long long ull;

// ---------------- scratch (device globals) ----------------
__device__ float g_z[(size_t)NN * DD];
__device__ float g_t1[(size_t)NN * DD];
__device__ float g_h[(size_t)NN * DD];
__device__ float g_feat[(size_t)GG * FF];
__device__ float g_feat2[(size_t)GG * FF];
__device__ float g_sum[7 * DD];     // per-layer BN stats
__device__ float g_sqsum[7 * DD];
// CSR scratch
__device__ int g_deg[NN];
__device__ int g_cursor[NN];
__device__ int g_rowptr[NN + 1];
__device__ int g_esrc[EE];
__device__ int g_bsum[256];

// ---------------- f32x2 helpers ----------------
__device__ __forceinline__ ull pk2(float x) {
    ull r;
    asm("mov.b64 %0, {%1,%2};" : "=l"(r) : "f"(x), "f"(x));
    return r;
}
__device__ __forceinline__ void fma2(ull& d, ull a, ull b) {
    asm("fma.rn.f32x2 %0, %1, %2, %0;" : "+l"(d) : "l"(a), "l"(b));
}
__device__ __forceinline__ void unpk(ull v, float& lo, float& hi) {
    asm("mov.b64 {%0,%1}, %2;" : "=f"(lo), "=f"(hi) : "l"(v));
}

// ---------------- zero everything mutable (one launch) ----------------
__global__ void k_zero_all() {
    int i = blockIdx.x * blockDim.x + threadIdx.x;
    if (i < GG * FF) g_feat[i] = 0.f;
    if (i < NN) { g_deg[i] = 0; g_cursor[i] = 0; }
    if (i < 7 * DD) { g_sum[i] = 0.f; g_sqsum[i] = 0.f; }
}

// ---------------- CSR build ----------------
__global__ void k_hist(const int* __restrict__ dst) {
    int e = blockIdx.x * blockDim.x + threadIdx.x;
    if (e < EE) atomicAdd(&g_deg[dst[e]], 1);
}
__global__ void k_scan1() {
    __shared__ int sh[256];
    int t = threadIdx.x;
    int i = blockIdx.x * 256 + t;
    int v = (i < NN) ? g_deg[i] : 0;
    sh[t] = v;
    __syncthreads();
#pragma unroll
    for (int off = 1; off < 256; off <<= 1) {
        int a = (t >= off) ? sh[t - off] : 0;
        __syncthreads();
        sh[t] += a;
        __syncthreads();
    }
    if (i < NN) g_rowptr[i] = sh[t] - v;
    if (t == 255) g_bsum[blockIdx.x] = sh[255];
}
__global__ void k_scan2() {
    __shared__ int sh[256];
    int t = threadIdx.x;
    int v = (t < NB_SCAN) ? g_bsum[t] : 0;
    sh[t] = v;
    __syncthreads();
#pragma unroll
    for (int off = 1; off < 256; off <<= 1) {
        int a = (t >= off) ? sh[t - off] : 0;
        __syncthreads();
        sh[t] += a;
        __syncthreads();
    }
    if (t < NB_SCAN) g_bsum[t] = sh[t] - v;
}
__global__ void k_scan3() {
    int i = blockIdx.x * blockDim.x + threadIdx.x;
    if (i < NN) g_rowptr[i] += g_bsum[i >> 8];
    if (i == 0) g_rowptr[NN] = EE;
}
__global__ void k_fill(const int* __restrict__ src, const int* __restrict__ dst) {
    int e = blockIdx.x * blockDim.x + threadIdx.x;
    if (e >= EE) return;
    int d = dst[e];
    int pos = atomicAdd(&g_cursor[d], 1);
    g_esrc[g_rowptr[d] + pos] = src[e];
}

// ---------------- aggregation: z[n] = h[n] + sum_in h[src] (1 warp/node) ----
__global__ void k_agg(const float* __restrict__ h) {
    int warp = (blockIdx.x * blockDim.x + threadIdx.x) >> 5;
    if (warp >= NN) return;
    int lane = threadIdx.x & 31;
    const float4* __restrict__ h4 = reinterpret_cast<const float4*>(h);
    float4 acc = h4[(size_t)warp * 32 + lane];
    int s = g_rowptr[warp], e = g_rowptr[warp + 1];
    int j = s;
    for (; j + 4 <= e; j += 4) {
        int i0 = g_esrc[j], i1 = g_esrc[j + 1], i2 = g_esrc[j + 2], i3 = g_esrc[j + 3];
        float4 v0 = h4[(size_t)i0 * 32 + lane];
        float4 v1 = h4[(size_t)i1 * 32 + lane];
        float4 v2 = h4[(size_t)i2 * 32 + lane];
        float4 v3 = h4[(size_t)i3 * 32 + lane];
        acc.x += v0.x + v1.x + v2.x + v3.x;
        acc.y += v0.y + v1.y + v2.y + v3.y;
        acc.z += v0.z + v1.z + v2.z + v3.z;
        acc.w += v0.w + v1.w + v2.w + v3.w;
    }
    for (; j < e; j++) {
        int i0 = g_esrc[j];
        float4 v0 = h4[(size_t)i0 * 32 + lane];
        acc.x += v0.x; acc.y += v0.y; acc.z += v0.z; acc.w += v0.w;
    }
    reinterpret_cast<float4*>(g_z)[(size_t)warp * 32 + lane] = acc;
}

// =====================================================================
// GEMM (R7 mainloop): [N,128] @ [128,128] + bias; BM=128, BK=16, 256 thr,
// 8x8 microtile, f32x2 accumulators, conflict-free c0/c1 B reads.
// MODE 1: fused BN column stats epilogue (per-layer arrays).
// MODE 2: BN scale/shift computed in smem prologue from layer stats,
//         BN+relu prologue on A, relu out, fused per-graph sum/max readout.
// =====================================================================
#define GEMM_SMEM (128 * 136 * 4)   // 69632 B

template <int MODE>
__global__ void __launch_bounds__(256, 2)
k_gemmY(const float* __restrict__ A, const float* __restrict__ W,
        const float* __restrict__ bias, float* __restrict__ C,
        const int* __restrict__ batch, int layer,
        const float* __restrict__ gamma, const float* __restrict__ beta) {
    extern __shared__ float sm[];
    float (*As)[16][128] = reinterpret_cast<float (*)[16][128]>(sm);
    float (*Bs)[16][128] = reinterpret_cast<float (*)[16][128]>(sm + 4096);
    __shared__ int bt[128];
    __shared__ float ssc[128], ssh[128];

    const int tid = threadIdx.x;
    const int tx = tid & 15, ty = tid >> 4;
    const int row0 = blockIdx.x * 128;
    const int c0 = tx * 4, c1 = 64 + tx * 4;

    if (MODE == 2 && tid < 128) {
        int gr = row0 + tid;
        bt[tid] = (gr < NN) ? batch[gr] : -1;
        // BN scale/shift from layer stats (replaces k_bnfin)
        float m = g_sum[layer * DD + tid] * (1.f / NN);
        float var = g_sqsum[layer * DD + tid] * (1.f / NN) - m * m;
        float sc = gamma[tid] * rsqrtf(var + BN_EPS);
        ssc[tid] = sc;
        ssh[tid] = beta[tid] - m * sc;
    }
    if (MODE == 2) __syncthreads();

    ull acc[8][4];
#pragma unroll
    for (int i = 0; i < 8; i++)
#pragma unroll
        for (int j = 0; j < 4; j++) acc[i][j] = 0ull;

    float4 ra[2], rb[2];

    auto ldg = [&](int k0) {
#pragma unroll
        for (int i = 0; i < 2; i++) {
            int v = tid + 256 * i;
            int r = v >> 2, kq = (v & 3) * 4;
            int gr = row0 + r;
            float4 val = make_float4(0.f, 0.f, 0.f, 0.f);
            if (gr < NN) val = *reinterpret_cast<const float4*>(A + (size_t)gr * DD + k0 + kq);
            if (MODE == 2) {
                float4 sc = *reinterpret_cast<const float4*>(&ssc[k0 + kq]);
                float4 sh = *reinterpret_cast<const float4*>(&ssh[k0 + kq]);
                val.x = fmaxf(fmaf(val.x, sc.x, sh.x), 0.f);
                val.y = fmaxf(fmaf(val.y, sc.y, sh.y), 0.f);
                val.z = fmaxf(fmaf(val.z, sc.z, sh.z), 0.f);
                val.w = fmaxf(fmaf(val.w, sc.w, sh.w), 0.f);
            }
            ra[i] = val;
            int kr = v >> 5, c4 = (v & 31) * 4;
            rb[i] = *reinterpret_cast<const float4*>(W + (size_t)(k0 + kr) * DD + c4);
        }
    };
    auto sts = [&](int s) {
#pragma unroll
        for (int i = 0; i < 2; i++) {
            int v = tid + 256 * i;
            int r = v >> 2, kq = (v & 3) * 4;
            As[s][kq + 0][r] = ra[i].x;
            As[s][kq + 1][r] = ra[i].y;
            As[s][kq + 2][r] = ra[i].z;
            As[s][kq + 3][r] = ra[i].w;
            int kr = v >> 5, c4 = (v & 31) * 4;
            *reinterpret_cast<float4*>(&Bs[s][kr][c4]) = rb[i];
        }
    };

    ldg(0);
    sts(0);
    __syncthreads();
    int s = 0;
#pragma unroll
    for (int t = 0; t < 8; t++) {
        if (t < 7) ldg((t + 1) * 16);
#pragma unroll
        for (int kk = 0; kk < 16; kk++) {
            float4 a0 = *reinterpret_cast<const float4*>(&As[s][kk][ty * 8]);
            float4 a1 = *reinterpret_cast<const float4*>(&As[s][kk][ty * 8 + 4]);
            ulonglong2 bv0 = *reinterpret_cast<const ulonglong2*>(&Bs[s][kk][c0]);
            ulonglong2 bv1 = *reinterpret_cast<const ulonglong2*>(&Bs[s][kk][c1]);
            ull bu[4] = {bv0.x, bv0.y, bv1.x, bv1.y};
            ull au[8];
            au[0] = pk2(a0.x); au[1] = pk2(a0.y); au[2] = pk2(a0.z); au[3] = pk2(a0.w);
            au[4] = pk2(a1.x); au[5] = pk2(a1.y); au[6] = pk2(a1.z); au[7] = pk2(a1.w);
#pragma unroll
            for (int i = 0; i < 8; i++) {
                fma2(acc[i][0], au[i], bu[0]);
                fma2(acc[i][1], au[i], bu[1]);
                fma2(acc[i][2], au[i], bu[2]);
                fma2(acc[i][3], au[i], bu[3]);
            }
        }
        if (t < 7) sts(s ^ 1);
        __syncthreads();
        s ^= 1;
    }

    // ---- epilogue: bias (+relu), store C ----
    float bb[8];
#pragma unroll
    for (int j = 0; j < 4; j++) { bb[j] = bias[c0 + j]; bb[4 + j] = bias[c1 + j]; }

    float o[8][8];
    float cs[8], cq[8];
    if (MODE == 1) {
#pragma unroll
        for (int j = 0; j < 8; j++) { cs[j] = 0.f; cq[j] = 0.f; }
    }
#pragma unroll
    for (int i = 0; i < 8; i++) {
#pragma unroll
        for (int j = 0; j < 4; j++) unpk(acc[i][j], o[i][2 * j], o[i][2 * j + 1]);
        int gr = row0 + ty * 8 + i;
        bool ok = (gr < NN);
#pragma unroll
        for (int j = 0; j < 8; j++) {
            float v = o[i][j] + bb[j];
            if (MODE == 2) v = fmaxf(v, 0.f);
            if (!ok) v = 0.f;
            o[i][j] = v;
        }
        if (ok) {
            float* cp = C + (size_t)gr * DD;
            *reinterpret_cast<float4*>(cp + c0) = *reinterpret_cast<const float4*>(&o[i][0]);
            *reinterpret_cast<float4*>(cp + c1) = *reinterpret_cast<const float4*>(&o[i][4]);
            if (MODE == 1) {
#pragma unroll
                for (int j = 0; j < 8; j++) {
                    cs[j] += o[i][j];
                    cq[j] = fmaf(o[i][j], o[i][j], cq[j]);
                }
            }
        }
    }

    __syncthreads();  // mainloop smem reads complete; reuse sm region

    if (MODE == 1) {
        float* reds = sm;            // [16][128]
        float* redq = sm + 2048;
#pragma unroll
        for (int j = 0; j < 4; j++) {
            reds[ty * 128 + c0 + j] = cs[j];
            reds[ty * 128 + c1 + j] = cs[4 + j];
            redq[ty * 128 + c0 + j] = cq[j];
            redq[ty * 128 + c1 + j] = cq[4 + j];
        }
        __syncthreads();
        if (tid < 128) {
            float ssum = 0.f, sq = 0.f;
#pragma unroll
            for (int r = 0; r < 16; r++) {
                ssum += reds[r * 128 + tid];
                sq += redq[r * 128 + tid];
            }
            atomicAdd(&g_sum[layer * DD + tid], ssum);
            atomicAdd(&g_sqsum[layer * DD + tid], sq);
        }
    } else {
        float* st = sm;   // [128][136]
#pragma unroll
        for (int i = 0; i < 8; i++) {
            int row = ty * 8 + i;
            *reinterpret_cast<float4*>(&st[row * 136 + c0]) = *reinterpret_cast<const float4*>(&o[i][0]);
            *reinterpret_cast<float4*>(&st[row * 136 + c1]) = *reinterpret_cast<const float4*>(&o[i][4]);
        }
        __syncthreads();
        int col = tid & 127;
        int half = tid >> 7;
        int rs = half * 64, re = rs + 64;
        float* fsum = g_feat + (size_t)layer * DD + col;
        float* fmax = g_feat + (size_t)(7 * DD + layer * DD) + col;
        int cur = -1;
        float ssum = 0.f, mx = 0.f;
        for (int r = rs; r < re; r++) {
            int g = bt[r];
            if (g != cur) {
                if (cur >= 0) {
                    atomicAdd(fsum + (size_t)cur * FF, ssum);
                    atomicMax((int*)(fmax + (size_t)cur * FF), __float_as_int(mx));
                }
                cur = g; ssum = 0.f; mx = 0.f;
            }
            if (g >= 0) {
                float v = st[r * 136 + col];
                ssum += v;
                mx = fmaxf(mx, v);
            }
        }
        if (cur >= 0) {
            atomicAdd(fsum + (size_t)cur * FF, ssum);
            atomicMax((int*)(fmax + (size_t)cur * FF), __float_as_int(mx));
        }
    }
}

// ---------------- MLP layer 1 (R7) ----------------
__global__ void __launch_bounds__(256, 4)
k_gemm_mlp(const float* __restrict__ Afeat, const float* __restrict__ W,
           const float* __restrict__ bias, float* __restrict__ C) {
    __shared__ float As[2][16][32];
    __shared__ float Bs[2][16][128];
    const int tid = threadIdx.x;
    const int tx = tid & 15, ty = tid >> 4;
    const int row0 = blockIdx.y * 32;
    const int col0 = blockIdx.x * 128;
    const int c0 = tx * 4, c1 = 64 + tx * 4;

    ull acc[2][4];
#pragma unroll
    for (int i = 0; i < 2; i++)
#pragma unroll
        for (int j = 0; j < 4; j++) acc[i][j] = 0ull;

    float4 ra;
    float4 rb[2];

    auto ldg = [&](int k0) {
        if (tid < 128) {
            int r = tid >> 2, kq = (tid & 3) * 4;
            ra = *reinterpret_cast<const float4*>(Afeat + (size_t)(row0 + r) * FF + k0 + kq);
        }
#pragma unroll
        for (int i = 0; i < 2; i++) {
            int v = tid + 256 * i;
            int kr = v >> 5, c4 = (v & 31) * 4;
            rb[i] = *reinterpret_cast<const float4*>(W + (size_t)(k0 + kr) * FF + col0 + c4);
        }
    };
    auto sts = [&](int s) {
        if (tid < 128) {
            int r = tid >> 2, kq = (tid & 3) * 4;
            As[s][kq + 0][r] = ra.x;
            As[s][kq + 1][r] = ra.y;
            As[s][kq + 2][r] = ra.z;
            As[s][kq + 3][r] = ra.w;
        }
#pragma unroll
        for (int i = 0; i < 2; i++) {
            int v = tid + 256 * i;
            int kr = v >> 5, c4 = (v & 31) * 4;
            *reinterpret_cast<float4*>(&Bs[s][kr][c4]) = rb[i];
        }
    };

    ldg(0);
    sts(0);
    __syncthreads();
    int s = 0;
    const int NT = FF / 16;  // 112
    for (int t = 0; t < NT; t++) {
        if (t < NT - 1) ldg((t + 1) * 16);
#pragma unroll
        for (int kk = 0; kk < 16; kk++) {
            ull a0 = pk2(As[s][kk][ty * 2]);
            ull a1 = pk2(As[s][kk][ty * 2 + 1]);
            ulonglong2 bv0 = *reinterpret_cast<const ulonglong2*>(&Bs[s][kk][c0]);
            ulonglong2 bv1 = *reinterpret_cast<const ulonglong2*>(&Bs[s][kk][c1]);
            ull bu[4] = {bv0.x, bv0.y, bv1.x, bv1.y};
#pragma unroll
            for (int j = 0; j < 4; j++) {
                fma2(acc[0][j], a0, bu[j]);
                fma2(acc[1][j], a1, bu[j]);
            }
        }
        if (t < NT - 1) sts(s ^ 1);
        __syncthreads();
        s ^= 1;
    }
#pragma unroll
    for (int i = 0; i < 2; i++) {
        int gr = row0 + ty * 2 + i;
        float* cp = C + (size_t)gr * FF + col0;
        float o[8];
#pragma unroll
        for (int j = 0; j < 4; j++) unpk(acc[i][j], o[2 * j], o[2 * j + 1]);
#pragma unroll
        for (int j = 0; j < 4; j++) {
            o[j]     = fmaxf(o[j] + bias[col0 + c0 + j], 0.f);
            o[4 + j] = fmaxf(o[4 + j] + bias[col0 + c1 + j], 0.f);
        }
        *reinterpret_cast<float4*>(cp + c0) = *reinterpret_cast<const float4*>(&o[0]);
        *reinterpret_cast<float4*>(cp + c1) = *reinterpret_cast<const float4*>(&o[4]);
    }
}

// ---------------- head ----------------
__global__ void k_head(const float* __restrict__ Wl2, const float* __restrict__ bl2,
                       float* __restrict__ out) {
    int g = blockIdx.x;
    float p = 0.f;
    for (int k = threadIdx.x; k < FF; k += 256)
        p += g_feat2[(size_t)g * FF + k] * Wl2[k];
    __shared__ float red[256];
    red[threadIdx.x] = p;
    __syncthreads();
    for (int off = 128; off > 0; off >>= 1) {
        if (threadIdx.x < off) red[threadIdx.x] += red[threadIdx.x + off];
        __syncthreads();
    }
    if (threadIdx.x == 0) {
        float l = red[0] + bl2[0];
        out[g] = 1.f / (1.f + expf(-l));
        out[GG + g] = l;
    }
}

// ---------------- launch ----------------
extern "C" void kernel_launch(void* const* d_in, const int* in_sizes, int n_in,
                              void* d_out, int out_size) {
    const float* x     = (const float*)d_in[0];
    const int*   ei    = (const int*)d_in[1];
    const int*   batch = (const int*)d_in[2];
    const float* W1    = (const float*)d_in[3];
    const float* b1    = (const float*)d_in[4];
    const float* gamma = (const float*)d_in[5];
    const float* beta  = (const float*)d_in[6];
    const float* W2    = (const float*)d_in[7];
    const float* b2    = (const float*)d_in[8];
    const float* Wl1   = (const float*)d_in[9];
    const float* bl1   = (const float*)d_in[10];
    const float* Wl2   = (const float*)d_in[11];
    const float* bl2   = (const float*)d_in[12];
    float* out = (float*)d_out;

    const int* src = ei;
    const int* dst = ei + EE;

    float *zp, *t1p, *hp, *featp, *feat2p;
    cudaGetSymbolAddress((void**)&zp, g_z);
    cudaGetSymbolAddress((void**)&t1p, g_t1);
    cudaGetSymbolAddress((void**)&hp, g_h);
    cudaGetSymbolAddress((void**)&featp, g_feat);
    cudaGetSymbolAddress((void**)&feat2p, g_feat2);

    cudaFuncSetAttribute(k_gemmY<1>, cudaFuncAttributeMaxDynamicSharedMemorySize, GEMM_SMEM);
    cudaFuncSetAttribute(k_gemmY<2>, cudaFuncAttributeMaxDynamicSharedMemorySize, GEMM_SMEM);

    // one zero pass: g_feat + CSR counters + per-layer BN stats
    k_zero_all<<<(GG * FF + 255) / 256, 256>>>();

    // CSR build
    k_hist<<<(EE + 255) / 256, 256>>>(dst);
    k_scan1<<<NB_SCAN, 256>>>();
    k_scan2<<<1, 256>>>();
    k_scan3<<<(NN + 255) / 256, 256>>>();
    k_fill<<<(EE + 255) / 256, 256>>>(src, dst);

    const int NBLK = (NN + 127) / 128;  // 391
    const float* hin = x;
    for (int l = 0; l < 7; l++) {
        k_agg<<<(NN * 32 + 255) / 256, 256>>>(hin);
        k_gemmY<1><<<NBLK, 256, GEMM_SMEM>>>(zp, W1 + (size_t)l * DD * DD,
                                             b1 + l * DD, t1p, nullptr, l,
                                             nullptr, nullptr);
        k_gemmY<2><<<NBLK, 256, GEMM_SMEM>>>(t1p, W2 + (size_t)l * DD * DD,
                                             b2 + l * DD, hp, batch, l,
                                             gamma + l * DD, beta + l * DD);
        hin = hp;
    }
    k_gemm_mlp<<<dim3(FF / 128, GG / 32), 256>>>(featp, Wl1, bl1, feat2p);
    k_head<<<GG, 256>>>(Wl2, bl2, out);
}